// round 2
// baseline (speedup 1.0000x reference)
#include <cuda_runtime.h>
#include <cuda_bf16.h>

// out[b,t,v] = sum_d x[b,t,d,v] * w[d] + bias
// x: (2, 512, 8, 32000) fp32 contiguous; w: (8,); b: (1,)
// out: (2, 512, 32000) fp32
//
// Pure HBM-streaming kernel: one thread per float4 of output.
// Each thread issues 8 independent float4 loads (stride 32000 floats apart),
// giving MLP=8 to hide DRAM latency; all loads/stores fully coalesced.

#define DEPTH   8
#define VROW4   8000              // 32000 floats / 4 per (b,t,d) row
#define TOTAL4  (2L * 512L * VROW4)   // 8,192,000 float4 outputs

__global__ __launch_bounds__(256) void ttm_kernel(
    const float4* __restrict__ x,
    const float*  __restrict__ w,
    const float*  __restrict__ bias,
    float4* __restrict__ out)
{
    long i = (long)blockIdx.x * blockDim.x + threadIdx.x;
    if (i >= TOTAL4) return;

    int row = (int)(i / VROW4);   // which (b,t) of 1024
    int v4  = (int)(i % VROW4);

    // weights: tiny, L1/L2-broadcast; load to registers once
    float wr[DEPTH];
#pragma unroll
    for (int d = 0; d < DEPTH; ++d) wr[d] = __ldg(&w[d]);
    float bb = __ldg(bias);

    const float4* p = x + (long)row * DEPTH * VROW4 + v4;

    float4 acc;
    acc.x = bb; acc.y = bb; acc.z = bb; acc.w = bb;

#pragma unroll
    for (int d = 0; d < DEPTH; ++d) {
        float4 t = __ldg(p + (long)d * VROW4);
        acc.x = fmaf(t.x, wr[d], acc.x);
        acc.y = fmaf(t.y, wr[d], acc.y);
        acc.z = fmaf(t.z, wr[d], acc.z);
        acc.w = fmaf(t.w, wr[d], acc.w);
    }

    out[i] = acc;
}

extern "C" void kernel_launch(void* const* d_in, const int* in_sizes, int n_in,
                              void* d_out, int out_size)
{
    const float4* x    = (const float4*)d_in[0];
    const float*  w    = (const float*) d_in[1];
    const float*  bias = (const float*) d_in[2];
    float4*       out  = (float4*)      d_out;

    const int threads = 256;
    const long blocks = (TOTAL4 + threads - 1) / threads;   // 32000
    ttm_kernel<<<(unsigned)blocks, threads>>>(x, w, bias, out);
}